// round 1
// baseline (speedup 1.0000x reference)
#include <cuda_runtime.h>
#include <cuda_bf16.h>

// ---------------------------------------------------------------------------
// GraphSAGE 2-layer forward.
//   agg1 = segment_mean(x[src] -> dst);  h1 = relu(x@Ws1 + agg1@Wn1 + b1)
//   agg2 = segment_mean(h1[src] -> dst); out = h1@Ws2 + agg2@Wn2 + b2
// N = 100000, E = 1e6, d_in=64, d_hid=128, d_out=64. fp32 everywhere.
// ---------------------------------------------------------------------------

#define N_NODES 100000
#define D_IN    64
#define D_HID   128
#define D_OUT   64

// Scratch (device globals; no allocation allowed)
__device__ float g_deg [N_NODES];
__device__ float g_agg1[N_NODES * D_IN];     // 25.6 MB
__device__ float g_h1  [N_NODES * D_HID];    // 51.2 MB
__device__ float g_agg2[N_NODES * D_HID];    // 51.2 MB

// ---------------------------------------------------------------------------
__global__ void zero_kernel(float* __restrict__ p, int n) {
    int i = blockIdx.x * blockDim.x + threadIdx.x;
    int stride = gridDim.x * blockDim.x;
    for (; i < n; i += stride) p[i] = 0.0f;
}

// Scatter layer-1: each edge contributes x[src] (64 floats) into agg1[dst].
// 16 threads per edge, one float4 each. Thread c==0 also bumps the degree.
__global__ void scatter1_kernel(const float4* __restrict__ x4,
                                const int* __restrict__ src,
                                const int* __restrict__ dst,
                                float* __restrict__ agg1,
                                float* __restrict__ deg,
                                int E) {
    int idx = blockIdx.x * blockDim.x + threadIdx.x;
    if (idx >= E * 16) return;
    int e = idx >> 4;
    int c = idx & 15;
    int s = src[e];
    int d = dst[e];
    float4 v = x4[s * 16 + c];
    float* p = &agg1[d * D_IN + c * 4];
    atomicAdd(p + 0, v.x);
    atomicAdd(p + 1, v.y);
    atomicAdd(p + 2, v.z);
    atomicAdd(p + 3, v.w);
    if (c == 0) atomicAdd(&deg[d], 1.0f);
}

// Scatter layer-2: each edge contributes h1[src] (128 floats) into agg2[dst].
__global__ void scatter2_kernel(const float4* __restrict__ h4,
                                const int* __restrict__ src,
                                const int* __restrict__ dst,
                                float* __restrict__ agg2,
                                int E) {
    int idx = blockIdx.x * blockDim.x + threadIdx.x;
    if (idx >= E * 32) return;
    int e = idx >> 5;
    int c = idx & 31;
    int s = src[e];
    int d = dst[e];
    float4 v = h4[s * 32 + c];
    float* p = &agg2[d * D_HID + c * 4];
    atomicAdd(p + 0, v.x);
    atomicAdd(p + 1, v.y);
    atomicAdd(p + 2, v.z);
    atomicAdd(p + 3, v.w);
}

// ---------------------------------------------------------------------------
// Fused layer: out[n] = act( in[n]@Ws + (agg[n]/max(deg,1))@Wn + b )
// Weights cached in dynamic smem; block processes NPB nodes per iteration,
// each thread owns 2 output columns (float2 weight loads).
// blockDim = 256 = NPB * (DOUTT/2)
// ---------------------------------------------------------------------------
template <int DINT, int DOUTT, bool RELU, int NPB>
__global__ __launch_bounds__(256)
void layer_kernel(const float* __restrict__ in,
                  const float* __restrict__ agg,
                  const float* __restrict__ deg,
                  const float* __restrict__ Ws,
                  const float* __restrict__ Wn,
                  const float* __restrict__ bias,
                  float* __restrict__ out,
                  int nNodes) {
    constexpr int TPN = DOUTT / 2;   // threads per node
    extern __shared__ float smem[];
    float* sWs = smem;                      // DINT*DOUTT
    float* sWn = sWs + DINT * DOUTT;        // DINT*DOUTT
    float* sB  = sWn + DINT * DOUTT;        // DOUTT
    float* sX  = sB + DOUTT;                // NPB*DINT
    float* sA  = sX + NPB * DINT;           // NPB*DINT

    const int tid = threadIdx.x;
    for (int i = tid; i < DINT * DOUTT; i += blockDim.x) {
        sWs[i] = Ws[i];
        sWn[i] = Wn[i];
    }
    for (int i = tid; i < DOUTT; i += blockDim.x) sB[i] = bias[i];
    __syncthreads();

    const int g = tid / TPN;   // node slot within block
    const int t = tid % TPN;   // column-pair index

    for (int base = blockIdx.x * NPB; base < nNodes; base += gridDim.x * NPB) {
        // Stage input rows (self + mean-normalized neighbor agg)
        for (int i = tid; i < NPB * DINT; i += blockDim.x) {
            int n = i / DINT, k = i % DINT;
            int node = base + n;
            float xv = 0.0f, av = 0.0f;
            if (node < nNodes) {
                xv = in[node * DINT + k];
                float d = deg[node];
                d = (d > 1.0f) ? d : 1.0f;
                av = agg[node * DINT + k] / d;
            }
            sX[n * DINT + k] = xv;
            sA[n * DINT + k] = av;
        }
        __syncthreads();

        int node = base + g;
        float acc0 = sB[2 * t];
        float acc1 = sB[2 * t + 1];
        const float* xr = &sX[g * DINT];
        const float* ar = &sA[g * DINT];
#pragma unroll 8
        for (int k = 0; k < DINT; k++) {
            float2 ws = *reinterpret_cast<const float2*>(&sWs[k * DOUTT + 2 * t]);
            float2 wn = *reinterpret_cast<const float2*>(&sWn[k * DOUTT + 2 * t]);
            float xv = xr[k];
            float av = ar[k];
            acc0 = fmaf(xv, ws.x, acc0);
            acc0 = fmaf(av, wn.x, acc0);
            acc1 = fmaf(xv, ws.y, acc1);
            acc1 = fmaf(av, wn.y, acc1);
        }
        if (node < nNodes) {
            if (RELU) {
                acc0 = fmaxf(acc0, 0.0f);
                acc1 = fmaxf(acc1, 0.0f);
            }
            *reinterpret_cast<float2*>(&out[node * DOUTT + 2 * t]) =
                make_float2(acc0, acc1);
        }
        __syncthreads();
    }
}

// ---------------------------------------------------------------------------
extern "C" void kernel_launch(void* const* d_in, const int* in_sizes, int n_in,
                              void* d_out, int out_size) {
    const float* x       = (const float*)d_in[0];
    const int*   src     = (const int*)d_in[1];
    const int*   dst     = (const int*)d_in[2];
    const float* w_self1 = (const float*)d_in[3];
    const float* w_neigh1= (const float*)d_in[4];
    const float* b1      = (const float*)d_in[5];
    const float* w_self2 = (const float*)d_in[6];
    const float* w_neigh2= (const float*)d_in[7];
    const float* b2      = (const float*)d_in[8];
    float* out = (float*)d_out;

    const int E = in_sizes[1];

    float *deg, *agg1, *h1, *agg2;
    cudaGetSymbolAddress((void**)&deg,  g_deg);
    cudaGetSymbolAddress((void**)&agg1, g_agg1);
    cudaGetSymbolAddress((void**)&h1,   g_h1);
    cudaGetSymbolAddress((void**)&agg2, g_agg2);

    // Dynamic smem sizes for the layer kernels
    constexpr int SMEM1 = (2 * D_IN * D_HID + D_HID + 2 * 4 * D_IN) * 4;   // ~68 KB
    constexpr int SMEM2 = (2 * D_HID * D_OUT + D_OUT + 2 * 8 * D_HID) * 4; // ~74 KB
    cudaFuncSetAttribute((const void*)layer_kernel<D_IN, D_HID, true, 4>,
                         cudaFuncAttributeMaxDynamicSharedMemorySize, SMEM1);
    cudaFuncSetAttribute((const void*)layer_kernel<D_HID, D_OUT, false, 8>,
                         cudaFuncAttributeMaxDynamicSharedMemorySize, SMEM2);

    // 1) zero scratch
    zero_kernel<<<1024, 256>>>(deg,  N_NODES);
    zero_kernel<<<4096, 256>>>(agg1, N_NODES * D_IN);
    zero_kernel<<<4096, 256>>>(agg2, N_NODES * D_HID);

    // 2) scatter layer 1 (+ degree)
    {
        int total = E * 16;
        scatter1_kernel<<<(total + 255) / 256, 256>>>(
            (const float4*)x, src, dst, agg1, deg, E);
    }

    // 3) layer 1 (fused GEMM + mean + bias + relu)
    layer_kernel<D_IN, D_HID, true, 4><<<444, 256, SMEM1>>>(
        x, agg1, deg, w_self1, w_neigh1, b1, h1, N_NODES);

    // 4) scatter layer 2
    {
        int total = E * 32;
        scatter2_kernel<<<(total + 255) / 256, 256>>>(
            (const float4*)h1, src, dst, agg2, E);
    }

    // 5) layer 2 (fused GEMM + mean + bias)
    layer_kernel<D_HID, D_OUT, false, 8><<<444, 256, SMEM2>>>(
        h1, agg2, deg, w_self2, w_neigh2, b2, out, N_NODES);
}

// round 2
// speedup vs baseline: 1.3651x; 1.3651x over previous
#include <cuda_runtime.h>
#include <cuda_bf16.h>

// ---------------------------------------------------------------------------
// GraphSAGE 2-layer forward, CSR-gather formulation (no fp32 atomics).
//   build CSR(dst) once per launch; for each layer:
//     aggmean[n] = mean_{e: dst=n} feat[src[e]]
//     out[n] = act( feat[n]@Ws + aggmean[n]@Wn + b )
// N = 100000, E = 1e6, d_in=64, d_hid=128, d_out=64. fp32.
// ---------------------------------------------------------------------------

#define N_NODES 100000
#define E_MAX   1000000
#define D_IN    64
#define D_HID   128
#define D_OUT   64

// Scratch (device globals; no allocation allowed)
__device__ int   g_cnt   [N_NODES];
__device__ int   g_rowptr[N_NODES + 1];
__device__ int   g_cursor[N_NODES];
__device__ int   g_csrsrc[E_MAX];
__device__ float g_agg1  [N_NODES * D_IN];     // mean-agg layer1 input
__device__ float g_h1    [N_NODES * D_HID];
__device__ float g_agg2  [N_NODES * D_HID];

// ---------------------------------------------------------------------------
__global__ void zero_int_kernel(int* __restrict__ p, int n) {
    int i = blockIdx.x * blockDim.x + threadIdx.x;
    if (i < n) p[i] = 0;
}

__global__ void count_kernel(const int* __restrict__ dst, int* __restrict__ cnt, int E) {
    int e = blockIdx.x * blockDim.x + threadIdx.x;
    if (e < E) atomicAdd(&cnt[dst[e]], 1);
}

// Single-block exclusive scan of cnt[0..n) -> row_ptr, cursor. row_ptr[n]=E.
__global__ __launch_bounds__(1024)
void scan_kernel(const int* __restrict__ cnt,
                 int* __restrict__ row_ptr,
                 int* __restrict__ cursor, int n) {
    __shared__ int sums[1024];
    const int tid = threadIdx.x;
    const int chunk = (n + 1023) / 1024;
    const int begin = tid * chunk;
    const int end = min(begin + chunk, n);

    int s = 0;
    for (int i = begin; i < end; i++) s += cnt[i];
    sums[tid] = s;
    __syncthreads();

    // Hillis-Steele inclusive scan
    for (int off = 1; off < 1024; off <<= 1) {
        int v = 0;
        if (tid >= off) v = sums[tid - off];
        __syncthreads();
        if (tid >= off) sums[tid] += v;
        __syncthreads();
    }

    int prefix = (tid == 0) ? 0 : sums[tid - 1];
    for (int i = begin; i < end; i++) {
        row_ptr[i] = prefix;
        cursor[i] = prefix;
        prefix += cnt[i];
    }
    if (tid == 1023) row_ptr[n] = sums[1023];
}

__global__ void fill_kernel(const int* __restrict__ src,
                            const int* __restrict__ dst,
                            int* __restrict__ cursor,
                            int* __restrict__ csr, int E) {
    int e = blockIdx.x * blockDim.x + threadIdx.x;
    if (e < E) {
        int pos = atomicAdd(&cursor[dst[e]], 1);
        csr[pos] = src[e];
    }
}

// ---------------------------------------------------------------------------
// Gather + mean: VPF float4s per feature row; VPF threads per node.
// blockDim = 256 -> 256/VPF nodes per block.
// ---------------------------------------------------------------------------
template <int VPF>
__global__ __launch_bounds__(256)
void gather_kernel(const float4* __restrict__ feat,
                   const int* __restrict__ csr,
                   const int* __restrict__ row_ptr,
                   float4* __restrict__ aggmean, int n) {
    const int tid = threadIdx.x;
    const int node = blockIdx.x * (256 / VPF) + tid / VPF;
    const int c = tid % VPF;
    if (node >= n) return;

    const int b = row_ptr[node];
    const int e = row_ptr[node + 1];
    float4 acc = make_float4(0.f, 0.f, 0.f, 0.f);
    for (int i = b; i < e; i++) {
        int s = csr[i];
        float4 v = feat[s * VPF + c];
        acc.x += v.x; acc.y += v.y; acc.z += v.z; acc.w += v.w;
    }
    int d = e - b;
    float inv = 1.0f / (float)(d > 1 ? d : 1);
    acc.x *= inv; acc.y *= inv; acc.z *= inv; acc.w *= inv;
    aggmean[node * VPF + c] = acc;
}

// ---------------------------------------------------------------------------
// Fused layer: out[n] = act( in[n]@Ws + aggmean[n]@Wn + b )
// Weights in smem; each thread owns 4 output columns (float4 weight loads).
// blockDim = 256 = NPB * (DOUT/4). Grid-stride over node tiles so weights are
// loaded only once per block.
// ---------------------------------------------------------------------------
template <int DINT, int DOUTT, bool RELU, int NPB>
__global__ __launch_bounds__(256)
void layer_kernel(const float* __restrict__ in,
                  const float* __restrict__ aggmean,
                  const float* __restrict__ Ws,
                  const float* __restrict__ Wn,
                  const float* __restrict__ bias,
                  float* __restrict__ out,
                  int nNodes) {
    constexpr int TPN = DOUTT / 4;       // threads per node
    constexpr int ROW = DINT + 4;        // padded smem row (floats)
    extern __shared__ float smem[];
    float* sWs = smem;                      // DINT*DOUTT
    float* sWn = sWs + DINT * DOUTT;        // DINT*DOUTT
    float* sB  = sWn + DINT * DOUTT;        // DOUTT
    float* sX  = sB + DOUTT;                // NPB*ROW
    float* sA  = sX + NPB * ROW;            // NPB*ROW

    const int tid = threadIdx.x;
    for (int i = tid; i < DINT * DOUTT; i += 256) {
        sWs[i] = Ws[i];
        sWn[i] = Wn[i];
    }
    for (int i = tid; i < DOUTT; i += 256) sB[i] = bias[i];
    __syncthreads();

    const int g = tid / TPN;   // node slot within block
    const int t = tid % TPN;   // column-quad index

    for (int base = blockIdx.x * NPB; base < nNodes; base += gridDim.x * NPB) {
        // Stage input rows (self + precomputed mean agg), float4 wide
        for (int i = tid; i < NPB * (DINT / 4); i += 256) {
            int n = i / (DINT / 4), k4 = i % (DINT / 4);
            int node = base + n;
            float4 xv = make_float4(0.f, 0.f, 0.f, 0.f);
            float4 av = xv;
            if (node < nNodes) {
                xv = reinterpret_cast<const float4*>(in)[node * (DINT / 4) + k4];
                av = reinterpret_cast<const float4*>(aggmean)[node * (DINT / 4) + k4];
            }
            reinterpret_cast<float4*>(&sX[n * ROW])[k4] = xv;
            reinterpret_cast<float4*>(&sA[n * ROW])[k4] = av;
        }
        __syncthreads();

        const int node = base + g;
        float4 acc = *reinterpret_cast<const float4*>(&sB[4 * t]);
        const float* xr = &sX[g * ROW];
        const float* ar = &sA[g * ROW];
#pragma unroll 8
        for (int k = 0; k < DINT; k++) {
            float4 ws = *reinterpret_cast<const float4*>(&sWs[k * DOUTT + 4 * t]);
            float4 wn = *reinterpret_cast<const float4*>(&sWn[k * DOUTT + 4 * t]);
            float xv = xr[k];
            float av = ar[k];
            acc.x = fmaf(xv, ws.x, acc.x); acc.x = fmaf(av, wn.x, acc.x);
            acc.y = fmaf(xv, ws.y, acc.y); acc.y = fmaf(av, wn.y, acc.y);
            acc.z = fmaf(xv, ws.z, acc.z); acc.z = fmaf(av, wn.z, acc.z);
            acc.w = fmaf(xv, ws.w, acc.w); acc.w = fmaf(av, wn.w, acc.w);
        }
        if (node < nNodes) {
            if (RELU) {
                acc.x = fmaxf(acc.x, 0.f); acc.y = fmaxf(acc.y, 0.f);
                acc.z = fmaxf(acc.z, 0.f); acc.w = fmaxf(acc.w, 0.f);
            }
            *reinterpret_cast<float4*>(&out[node * DOUTT + 4 * t]) = acc;
        }
        __syncthreads();
    }
}

// ---------------------------------------------------------------------------
extern "C" void kernel_launch(void* const* d_in, const int* in_sizes, int n_in,
                              void* d_out, int out_size) {
    const float* x       = (const float*)d_in[0];
    const int*   src     = (const int*)d_in[1];
    const int*   dst     = (const int*)d_in[2];
    const float* w_self1 = (const float*)d_in[3];
    const float* w_neigh1= (const float*)d_in[4];
    const float* b1      = (const float*)d_in[5];
    const float* w_self2 = (const float*)d_in[6];
    const float* w_neigh2= (const float*)d_in[7];
    const float* b2      = (const float*)d_in[8];
    float* out = (float*)d_out;

    const int E = in_sizes[1];

    int *cnt, *rowptr, *cursor, *csrsrc;
    float *agg1, *h1, *agg2;
    cudaGetSymbolAddress((void**)&cnt,    g_cnt);
    cudaGetSymbolAddress((void**)&rowptr, g_rowptr);
    cudaGetSymbolAddress((void**)&cursor, g_cursor);
    cudaGetSymbolAddress((void**)&csrsrc, g_csrsrc);
    cudaGetSymbolAddress((void**)&agg1,   g_agg1);
    cudaGetSymbolAddress((void**)&h1,     g_h1);
    cudaGetSymbolAddress((void**)&agg2,   g_agg2);

    constexpr int SMEM1 = (2 * D_IN * D_HID + D_HID + 2 * 8 * (D_IN + 4)) * 4;
    constexpr int SMEM2 = (2 * D_HID * D_OUT + D_OUT + 2 * 16 * (D_HID + 4)) * 4;
    cudaFuncSetAttribute((const void*)layer_kernel<D_IN, D_HID, true, 8>,
                         cudaFuncAttributeMaxDynamicSharedMemorySize, SMEM1);
    cudaFuncSetAttribute((const void*)layer_kernel<D_HID, D_OUT, false, 16>,
                         cudaFuncAttributeMaxDynamicSharedMemorySize, SMEM2);

    // --- CSR build (reused by both layers) ---
    zero_int_kernel<<<(N_NODES + 255) / 256, 256>>>(cnt, N_NODES);
    count_kernel<<<(E + 255) / 256, 256>>>(dst, cnt, E);
    scan_kernel<<<1, 1024>>>(cnt, rowptr, cursor, N_NODES);
    fill_kernel<<<(E + 255) / 256, 256>>>(src, dst, cursor, csrsrc, E);

    // --- Layer 1 ---
    gather_kernel<D_IN / 4><<<(N_NODES + 15) / 16, 256>>>(
        (const float4*)x, csrsrc, rowptr, (float4*)agg1, N_NODES);
    layer_kernel<D_IN, D_HID, true, 8><<<296, 256, SMEM1>>>(
        x, agg1, w_self1, w_neigh1, b1, h1, N_NODES);

    // --- Layer 2 ---
    gather_kernel<D_HID / 4><<<(N_NODES + 7) / 8, 256>>>(
        (const float4*)h1, csrsrc, rowptr, (float4*)agg2, N_NODES);
    layer_kernel<D_HID, D_OUT, false, 16><<<296, 256, SMEM2>>>(
        h1, agg2, w_self2, w_neigh2, b2, out, N_NODES);
}

// round 4
// speedup vs baseline: 2.4994x; 1.8309x over previous
#include <cuda_runtime.h>
#include <cuda_bf16.h>
#include <mma.h>
#include <cstdint>

using namespace nvcuda;

// ---------------------------------------------------------------------------
// GraphSAGE 2-layer forward. CSR-gather aggregation + wmma bf16 split GEMM.
//   out = act( [x|agg] @ [Ws;Wn] + b ), computed as Ah@Wh + Al@Wh + Ah@Wl
//   (hi/lo bf16 split of fp32; dropped Al@Wl term ~2^-18 relative)
// N = 100000, E = 1e6, d_in=64, d_hid=128, d_out=64.
// ---------------------------------------------------------------------------

#define N_NODES 100000
#define E_MAX   1000000
#define D_IN    64
#define D_HID   128
#define D_OUT   64

// Scratch (device globals; no allocation allowed)
__device__ int   g_cnt   [N_NODES];
__device__ int   g_rowptr[N_NODES + 1];
__device__ int   g_cursor[N_NODES];
__device__ int   g_csrsrc[E_MAX];
__device__ float g_agg1  [N_NODES * D_IN];
__device__ float g_h1    [N_NODES * D_HID];
__device__ float g_agg2  [N_NODES * D_HID];
__device__ __nv_bfloat16 g_B1h[128 * 128];   // [K=128][N=128] hi(W1)
__device__ __nv_bfloat16 g_B1l[128 * 128];   // lo(W1)
__device__ __nv_bfloat16 g_B2h[256 * 64];    // [K=256][N=64]  hi(W2)
__device__ __nv_bfloat16 g_B2l[256 * 64];    // lo(W2)

// bf16 hi/lo packing helpers
__device__ __forceinline__ uint32_t bfu(__nv_bfloat16 h) {
    return (uint32_t)__bfloat16_as_ushort(h);
}
__device__ __forceinline__ uint32_t pack_hi2(float a, float b) {
    return bfu(__float2bfloat16_rn(a)) | (bfu(__float2bfloat16_rn(b)) << 16);
}
__device__ __forceinline__ uint32_t pack_lo2(float a, float b) {
    __nv_bfloat16 ha = __float2bfloat16_rn(a), hb = __float2bfloat16_rn(b);
    float ra = a - __bfloat162float(ha);
    float rb = b - __bfloat162float(hb);
    return bfu(__float2bfloat16_rn(ra)) | (bfu(__float2bfloat16_rn(rb)) << 16);
}

// ===========================================================================
// CSR build
// ===========================================================================
__global__ void zero_int_kernel(int* __restrict__ p, int n) {
    int i = blockIdx.x * blockDim.x + threadIdx.x;
    if (i < n) p[i] = 0;
}

__global__ void count_kernel(const int* __restrict__ dst, int* __restrict__ cnt, int E) {
    int e = blockIdx.x * blockDim.x + threadIdx.x;
    if (e < E) atomicAdd(&cnt[dst[e]], 1);
}

__global__ __launch_bounds__(1024)
void scan_kernel(const int* __restrict__ cnt,
                 int* __restrict__ row_ptr,
                 int* __restrict__ cursor, int n) {
    __shared__ int sums[1024];
    const int tid = threadIdx.x;
    const int chunk = (n + 1023) / 1024;
    const int begin = tid * chunk;
    const int end = min(begin + chunk, n);
    int s = 0;
    for (int i = begin; i < end; i++) s += cnt[i];
    sums[tid] = s;
    __syncthreads();
    for (int off = 1; off < 1024; off <<= 1) {
        int v = 0;
        if (tid >= off) v = sums[tid - off];
        __syncthreads();
        if (tid >= off) sums[tid] += v;
        __syncthreads();
    }
    int prefix = (tid == 0) ? 0 : sums[tid - 1];
    for (int i = begin; i < end; i++) {
        row_ptr[i] = prefix;
        cursor[i] = prefix;
        prefix += cnt[i];
    }
    if (tid == 1023) row_ptr[n] = sums[1023];
}

__global__ void fill_kernel(const int* __restrict__ src,
                            const int* __restrict__ dst,
                            int* __restrict__ cursor,
                            int* __restrict__ csr, int E) {
    int e = blockIdx.x * blockDim.x + threadIdx.x;
    if (e < E) {
        int pos = atomicAdd(&cursor[dst[e]], 1);
        csr[pos] = src[e];
    }
}

// ===========================================================================
// Gather + mean (VPF float4s per feature row; VPF threads per node)
// ===========================================================================
template <int VPF>
__global__ __launch_bounds__(256)
void gather_kernel(const float4* __restrict__ feat,
                   const int* __restrict__ csr,
                   const int* __restrict__ row_ptr,
                   float4* __restrict__ aggmean, int n) {
    const int tid = threadIdx.x;
    const int node = blockIdx.x * (256 / VPF) + tid / VPF;
    const int c = tid % VPF;
    if (node >= n) return;
    const int b = row_ptr[node];
    const int e = row_ptr[node + 1];
    float4 acc = make_float4(0.f, 0.f, 0.f, 0.f);
#pragma unroll 4
    for (int i = b; i < e; i++) {
        int s = __ldg(&csr[i]);
        float4 v = __ldg(&feat[s * VPF + c]);
        acc.x += v.x; acc.y += v.y; acc.z += v.z; acc.w += v.w;
    }
    int d = e - b;
    float inv = 1.0f / (float)(d > 1 ? d : 1);
    acc.x *= inv; acc.y *= inv; acc.z *= inv; acc.w *= inv;
    aggmean[node * VPF + c] = acc;
}

// ===========================================================================
// Weight prep: W = [Ws; Wn] stacked -> hi/lo bf16, row-major [DK2][NOUT]
// ===========================================================================
template <int DK2, int NOUT>
__global__ void wprep_kernel(const float* __restrict__ ws,
                             const float* __restrict__ wn,
                             __nv_bfloat16* __restrict__ Bh,
                             __nv_bfloat16* __restrict__ Bl) {
    int i = blockIdx.x * blockDim.x + threadIdx.x;
    if (i >= DK2 * NOUT) return;
    int k = i / NOUT, n = i % NOUT;
    float w = (k < DK2 / 2) ? ws[k * NOUT + n] : wn[(k - DK2 / 2) * NOUT + n];
    __nv_bfloat16 hi = __float2bfloat16_rn(w);
    Bh[i] = hi;
    Bl[i] = __float2bfloat16_rn(w - __bfloat162float(hi));
}

// ===========================================================================
// Fused layer via wmma bf16 split GEMM.
// CTA = 128 nodes x NOUT, 8 warps. Warp tile: (WROWS*16) x (WCOLS*16).
// K processed in NCHUNK chunks of 64 source columns; A converted fp32 ->
// hi/lo bf16 into smem per chunk; B hi/lo chunk staged into smem.
// acc initialized from replicated-bias tile; ReLU elementwise on fragments.
// ===========================================================================
template <int NOUT, int WROWS, int WCOLS, int NCHUNK, int LAYER, bool RELU>
__global__ __launch_bounds__(256)
void wmma_layer_kernel(const float* __restrict__ self,
                       const float* __restrict__ agg,
                       const __nv_bfloat16* __restrict__ Bh,
                       const __nv_bfloat16* __restrict__ Bl,
                       const float* __restrict__ bias,
                       float* __restrict__ out, int nNodes) {
    constexpr int LD    = (LAYER == 1) ? 64 : 128;   // fp32 source row stride
    constexpr int ASTR  = 72;                        // smem A row stride (bf16)
    constexpr int BSTR  = NOUT + 8;                  // smem B row stride (bf16)
    constexpr int COLG  = NOUT / (WCOLS * 16);       // warp col groups

    extern __shared__ __align__(16) char smem_raw[];
    __nv_bfloat16* sAh = (__nv_bfloat16*)smem_raw;          // 128 x ASTR
    __nv_bfloat16* sAl = sAh + 128 * ASTR;                  // 128 x ASTR
    __nv_bfloat16* sBh = sAl + 128 * ASTR;                  // 64 x BSTR
    __nv_bfloat16* sBl = sBh + 64 * BSTR;                   // 64 x BSTR
    float*         sBias = (float*)(sBl + 64 * BSTR);       // 16 x NOUT

    const int tid = threadIdx.x;
    const int wid = tid >> 5;
    const int rowg = wid / COLG;        // warp row group
    const int colg = wid % COLG;        // warp col group
    const int base = blockIdx.x * 128;

    // Replicated bias tile (for accumulator init)
    for (int i = tid; i < 16 * NOUT; i += 256) sBias[i] = bias[i % NOUT];
    __syncthreads();

    wmma::fragment<wmma::accumulator, 16, 16, 16, float> acc[WROWS][WCOLS];
#pragma unroll
    for (int r = 0; r < WROWS; r++)
#pragma unroll
        for (int c = 0; c < WCOLS; c++)
            wmma::load_matrix_sync(acc[r][c],
                sBias + (colg * WCOLS + c) * 16, NOUT, wmma::mem_row_major);

    for (int kc = 0; kc < NCHUNK; kc++) {
        // source selection for this 64-col chunk
        const float* srcp;
        int coloff;
        if (LAYER == 1) { srcp = kc ? agg : self; coloff = 0; }
        else            { srcp = (kc < 2) ? self : agg; coloff = (kc & 1) * 64; }

        __syncthreads();   // previous chunk's frag loads done before overwrite

        // ---- stage A: 128 x 64 fp32 -> hi/lo bf16 ----
#pragma unroll
        for (int jj = tid; jj < 2048; jj += 256) {   // float4 index
            int m = jj >> 4, c4 = jj & 15;
            int node = base + m;
            float4 v = make_float4(0.f, 0.f, 0.f, 0.f);
            if (node < nNodes)
                v = *reinterpret_cast<const float4*>(
                        srcp + (size_t)node * LD + coloff + c4 * 4);
            uint2 hp = make_uint2(pack_hi2(v.x, v.y), pack_hi2(v.z, v.w));
            uint2 lp = make_uint2(pack_lo2(v.x, v.y), pack_lo2(v.z, v.w));
            *reinterpret_cast<uint2*>(&sAh[m * ASTR + c4 * 4]) = hp;
            *reinterpret_cast<uint2*>(&sAl[m * ASTR + c4 * 4]) = lp;
        }
        // ---- stage B: 64 x NOUT hi/lo bf16 from global ----
#pragma unroll
        for (int jj = tid; jj < 64 * NOUT / 4; jj += 256) {
            int r = jj / (NOUT / 4), c4 = jj % (NOUT / 4);
            size_t g = (size_t)(kc * 64 + r) * NOUT + c4 * 4;
            *reinterpret_cast<uint2*>(&sBh[r * BSTR + c4 * 4]) =
                *reinterpret_cast<const uint2*>(&Bh[g]);
            *reinterpret_cast<uint2*>(&sBl[r * BSTR + c4 * 4]) =
                *reinterpret_cast<const uint2*>(&Bl[g]);
        }
        __syncthreads();

        // ---- MMA over 4 k-steps of 16 ----
#pragma unroll
        for (int kk = 0; kk < 4; kk++) {
            wmma::fragment<wmma::matrix_a, 16, 16, 16, __nv_bfloat16, wmma::row_major> ah[WROWS], al[WROWS];
#pragma unroll
            for (int r = 0; r < WROWS; r++) {
                int rr = (rowg * WROWS + r) * 16;
                wmma::load_matrix_sync(ah[r], sAh + rr * ASTR + kk * 16, ASTR);
                wmma::load_matrix_sync(al[r], sAl + rr * ASTR + kk * 16, ASTR);
            }
#pragma unroll
            for (int c = 0; c < WCOLS; c++) {
                wmma::fragment<wmma::matrix_b, 16, 16, 16, __nv_bfloat16, wmma::row_major> bh, bl;
                int cc = (colg * WCOLS + c) * 16;
                wmma::load_matrix_sync(bh, sBh + kk * 16 * BSTR + cc, BSTR);
                wmma::load_matrix_sync(bl, sBl + kk * 16 * BSTR + cc, BSTR);
#pragma unroll
                for (int r = 0; r < WROWS; r++) {
                    wmma::mma_sync(acc[r][c], ah[r], bh, acc[r][c]);
                    wmma::mma_sync(acc[r][c], al[r], bh, acc[r][c]);
                    wmma::mma_sync(acc[r][c], ah[r], bl, acc[r][c]);
                }
            }
        }
    }

    // ---- epilogue: relu + store (16 | 100000, so tiles are all-or-nothing) ----
#pragma unroll
    for (int r = 0; r < WROWS; r++) {
        int rbase = base + (rowg * WROWS + r) * 16;
        if (rbase < nNodes) {
#pragma unroll
            for (int c = 0; c < WCOLS; c++) {
                if (RELU) {
#pragma unroll
                    for (int i = 0; i < acc[r][c].num_elements; i++)
                        acc[r][c].x[i] = fmaxf(acc[r][c].x[i], 0.f);
                }
                wmma::store_matrix_sync(
                    out + (size_t)rbase * NOUT + (colg * WCOLS + c) * 16,
                    acc[r][c], NOUT, wmma::mem_row_major);
            }
        }
    }
}

// ===========================================================================
extern "C" void kernel_launch(void* const* d_in, const int* in_sizes, int n_in,
                              void* d_out, int out_size) {
    const float* x        = (const float*)d_in[0];
    const int*   src      = (const int*)d_in[1];
    const int*   dst      = (const int*)d_in[2];
    const float* w_self1  = (const float*)d_in[3];
    const float* w_neigh1 = (const float*)d_in[4];
    const float* b1       = (const float*)d_in[5];
    const float* w_self2  = (const float*)d_in[6];
    const float* w_neigh2 = (const float*)d_in[7];
    const float* b2       = (const float*)d_in[8];
    float* out = (float*)d_out;

    const int E = in_sizes[1];

    int *cnt, *rowptr, *cursor, *csrsrc;
    float *agg1, *h1, *agg2;
    __nv_bfloat16 *B1h, *B1l, *B2h, *B2l;
    cudaGetSymbolAddress((void**)&cnt,    g_cnt);
    cudaGetSymbolAddress((void**)&rowptr, g_rowptr);
    cudaGetSymbolAddress((void**)&cursor, g_cursor);
    cudaGetSymbolAddress((void**)&csrsrc, g_csrsrc);
    cudaGetSymbolAddress((void**)&agg1,   g_agg1);
    cudaGetSymbolAddress((void**)&h1,     g_h1);
    cudaGetSymbolAddress((void**)&agg2,   g_agg2);
    cudaGetSymbolAddress((void**)&B1h,    g_B1h);
    cudaGetSymbolAddress((void**)&B1l,    g_B1l);
    cudaGetSymbolAddress((void**)&B2h,    g_B2h);
    cudaGetSymbolAddress((void**)&B2l,    g_B2l);

    // smem: A(2x128x72) + B(2x64x(NOUT+8)) in bf16, bias 16xNOUT fp32
    constexpr int SMEM_L1 = (2 * 128 * 72 + 2 * 64 * (128 + 8)) * 2 + 16 * 128 * 4; // 79872
    constexpr int SMEM_L2 = (2 * 128 * 72 + 2 * 64 * (64 + 8)) * 2 + 16 * 64 * 4;   // 59392
    cudaFuncSetAttribute((const void*)wmma_layer_kernel<D_HID, 2, 4, 2, 1, true>,
                         cudaFuncAttributeMaxDynamicSharedMemorySize, SMEM_L1);
    cudaFuncSetAttribute((const void*)wmma_layer_kernel<D_OUT, 1, 4, 4, 2, false>,
                         cudaFuncAttributeMaxDynamicSharedMemorySize, SMEM_L2);

    const int nTiles = (N_NODES + 127) / 128;   // 782

    // --- CSR build (reused by both layers) ---
    zero_int_kernel<<<(N_NODES + 255) / 256, 256>>>(cnt, N_NODES);
    count_kernel<<<(E + 255) / 256, 256>>>(dst, cnt, E);
    scan_kernel<<<1, 1024>>>(cnt, rowptr, cursor, N_NODES);
    fill_kernel<<<(E + 255) / 256, 256>>>(src, dst, cursor, csrsrc, E);

    // --- weight prep (tiny) ---
    wprep_kernel<128, 128><<<(128 * 128 + 255) / 256, 256>>>(w_self1, w_neigh1, B1h, B1l);
    wprep_kernel<256, 64><<<(256 * 64 + 255) / 256, 256>>>(w_self2, w_neigh2, B2h, B2l);

    // --- Layer 1 ---
    gather_kernel<D_IN / 4><<<(N_NODES + 15) / 16, 256>>>(
        (const float4*)x, csrsrc, rowptr, (float4*)agg1, N_NODES);
    wmma_layer_kernel<D_HID, 2, 4, 2, 1, true><<<nTiles, 256, SMEM_L1>>>(
        x, agg1, B1h, B1l, b1, h1, N_NODES);

    // --- Layer 2 ---
    gather_kernel<D_HID / 4><<<(N_NODES + 7) / 8, 256>>>(
        (const float4*)h1, csrsrc, rowptr, (float4*)agg2, N_NODES);
    wmma_layer_kernel<D_OUT, 1, 4, 4, 2, false><<<nTiles, 256, SMEM_L2>>>(
        h1, agg2, B2h, B2l, b2, out, N_NODES);
}